// round 4
// baseline (speedup 1.0000x reference)
#include <cuda_runtime.h>

typedef unsigned long long ull;

#define N_ROWS 1024
#define T_LEN  2048
#define E_NUM  16384
#define K_TAPS 32
#define TPB    256
#define TOUT   8              // outputs per thread (t0 = 8*tid)
#define MAX_B  96             // max experts per dst bucket

// Swizzle on float4 index: conflict-free for lane-stride-4 float4 window loads.
__device__ __forceinline__ int sw(int f4) { return f4 ^ ((f4 >> 2) & 7); }

// Packed dual fp32 FMA: acc.{lo,hi} += a.{lo,hi} * b.{lo,hi}
__device__ __forceinline__ void ffma2(ull& acc, ull a, ull b) {
    asm("fma.rn.f32x2 %0, %1, %2, %0;" : "+l"(acc) : "l"(a), "l"(b));
}

// ---------------------------------------------------------------------------
// One block per dst row n. Phase A: scan dst[] (cache-resident), build this
// row's expert list. Phase B: experts processed in PAIRS; the two rows are
// interleaved in smem as float2 so fma.rn.f32x2 computes both experts per
// issue (no operand packing). Register double-buffered prefetch. Phase C:
// out = x[n] + acc.lo + acc.hi.
// ---------------------------------------------------------------------------
__global__ __launch_bounds__(TPB, 2)
void conv_route_kernel(const float* __restrict__ x,
                       const float* __restrict__ w,
                       const int*   __restrict__ src,
                       const int*   __restrict__ dst,
                       float*       __restrict__ out) {
    // Interleaved pair row: logical float2 X2[i], i=0..2079 (i<32 = causal halo).
    // Stored as swizzled float4 (2 float2 each): 1040 float4 = 16.6 KB.
    __shared__ __align__(128) float4 xs4[1040];
    __shared__ __align__(8)   float2 wsh2[K_TAPS];
    __shared__ int lst[MAX_B];
    __shared__ int scn[TPB];

    const int tid = threadIdx.x;
    const int n   = blockIdx.x;

    if (tid < 16) xs4[sw(tid)] = make_float4(0.f, 0.f, 0.f, 0.f);   // halo

    // ---------------- Phase A: routing discovery --------------------------
    const int4* d4 = (const int4*)dst;
    int cnt = 0;
#pragma unroll 8
    for (int c = 0; c < 16; ++c) {
        int4 v = d4[tid * 16 + c];
        cnt += (v.x == n) + (v.y == n) + (v.z == n) + (v.w == n);
    }
    scn[tid] = cnt;
    __syncthreads();
    for (int ofs = 1; ofs < TPB; ofs <<= 1) {            // Hillis-Steele scan
        int a = (tid >= ofs) ? scn[tid - ofs] : 0;
        __syncthreads();
        scn[tid] += a;
        __syncthreads();
    }
    int excl  = scn[tid] - cnt;
    int total = scn[TPB - 1];
    if (total > MAX_B) total = MAX_B;
    {
        int pos = excl;
#pragma unroll 8
        for (int c = 0; c < 16; ++c) {
            int4 v = d4[tid * 16 + c];
            int  e0 = tid * 64 + c * 4;
            if (v.x == n && pos < MAX_B) lst[pos++] = e0;
            if (v.y == n && pos < MAX_B) lst[pos++] = e0 + 1;
            if (v.z == n && pos < MAX_B) lst[pos++] = e0 + 2;
            if (v.w == n && pos < MAX_B) lst[pos++] = e0 + 3;
        }
    }
    __syncthreads();

    const int pairs = (total + 1) >> 1;

    ull acc[TOUT];
#pragma unroll
    for (int j = 0; j < TOUT; ++j) acc[j] = 0ull;

    // ---------------- Phase B: paired conv --------------------------------
    // Prefetch pair 0: two rows (4 float4/thread) + one weight lane/thread.
    float4 f0a, f0b, f1a, f1b;
    float  wreg = 0.0f;
    if (pairs > 0) {
        int e0 = lst[0];
        int e1 = (total > 1) ? lst[1] : e0;
        const float4* r0 = (const float4*)(x + (size_t)src[e0] * T_LEN);
        const float4* r1 = (const float4*)(x + (size_t)src[e1] * T_LEN);
        f0a = r0[tid]; f0b = r0[tid + 256];
        f1a = r1[tid]; f1b = r1[tid + 256];
        if      (tid < K_TAPS)     wreg = w[e0 * K_TAPS + tid];
        else if (tid < 2 * K_TAPS) wreg = (total > 1) ? w[e1 * K_TAPS + (tid - K_TAPS)] : 0.f;
    }

    const char* xsb = (const char*)xs4;

    for (int p = 0; p < pairs; ++p) {
        __syncthreads();                                  // prior reads done
        // Publish interleaved: f0a/f1a cover t=4*tid..+3 -> float2 i=32+t.
        xs4[sw(16 + 2 * tid)]     = make_float4(f0a.x, f1a.x, f0a.y, f1a.y);
        xs4[sw(16 + 2 * tid + 1)] = make_float4(f0a.z, f1a.z, f0a.w, f1a.w);
        xs4[sw(528 + 2 * tid)]    = make_float4(f0b.x, f1b.x, f0b.y, f1b.y);
        xs4[sw(528 + 2 * tid + 1)]= make_float4(f0b.z, f1b.z, f0b.w, f1b.w);
        if      (tid < K_TAPS)     wsh2[tid].x = wreg;
        else if (tid < 2 * K_TAPS) wsh2[tid - K_TAPS].y = wreg;
        __syncthreads();

        if (p + 1 < pairs) {                              // prefetch next pair
            int  e0 = lst[2 * p + 2];
            bool v1 = (2 * p + 3 < total);
            int  e1 = v1 ? lst[2 * p + 3] : e0;
            const float4* r0 = (const float4*)(x + (size_t)src[e0] * T_LEN);
            const float4* r1 = (const float4*)(x + (size_t)src[e1] * T_LEN);
            f0a = r0[tid]; f0b = r0[tid + 256];
            f1a = r1[tid]; f1b = r1[tid + 256];
            if      (tid < K_TAPS)     wreg = w[e0 * K_TAPS + tid];
            else if (tid < 2 * K_TAPS) wreg = v1 ? w[e1 * K_TAPS + (tid - K_TAPS)] : 0.f;
        }

        // k split in two 16-tap halves. Half h uses window float2
        // X2[i], i = ibase + u, u = 1..23, ibase = 8*tid + 16 - 16h.
        // Load 12 float4 (= 24 float2) covering u = 0..23; zero repacking:
        // each LDS.128 lands as two aligned 64-bit lane-pairs.
#pragma unroll
        for (int h = 1; h >= 0; --h) {
            ull xw[24];
            const int fbase = 4 * tid + 8 - 8 * h;        // = ibase/2
#pragma unroll
            for (int c = 0; c < 12; ++c) {
                double2 v = *(const double2*)(xsb + 16 * sw(fbase + c));
                xw[2 * c]     = __double_as_longlong(v.x);
                xw[2 * c + 1] = __double_as_longlong(v.y);
            }
#pragma unroll
            for (int kq = 0; kq < 16; ++kq) {
                ull wv = *(const ull*)&wsh2[16 * h + kq];
#pragma unroll
                for (int j = 0; j < TOUT; ++j)
                    ffma2(acc[j], xw[16 + j - kq], wv);
            }
        }
    }

    // ---------------- Phase C: epilogue -----------------------------------
    const float4* xrow = (const float4*)(x + (size_t)n * T_LEN);
    float4*       orow = (float4*)(out + (size_t)n * T_LEN);
#pragma unroll
    for (int q = 0; q < 2; ++q) {
        float4 a = xrow[2 * tid + q];
        float2 p0 = *(float2*)&acc[4 * q + 0];
        float2 p1 = *(float2*)&acc[4 * q + 1];
        float2 p2 = *(float2*)&acc[4 * q + 2];
        float2 p3 = *(float2*)&acc[4 * q + 3];
        a.x += p0.x + p0.y;
        a.y += p1.x + p1.y;
        a.z += p2.x + p2.y;
        a.w += p3.x + p3.y;
        orow[2 * tid + q] = a;
    }
}

// ---------------------------------------------------------------------------
extern "C" void kernel_launch(void* const* d_in, const int* in_sizes, int n_in,
                              void* d_out, int out_size) {
    const float* x   = (const float*)d_in[0];
    const float* w   = (const float*)d_in[1];
    const int*   src = (const int*)d_in[2];
    const int*   dst = (const int*)d_in[3];
    float*       out = (float*)d_out;

    conv_route_kernel<<<N_ROWS, TPB>>>(x, w, src, dst, out);
}

// round 6
// speedup vs baseline: 1.1999x; 1.1999x over previous
#include <cuda_runtime.h>

#define N_ROWS 1024
#define T_LEN  2048
#define E_NUM  16384
#define K_TAPS 32
#define TPB    128            // threads per block
#define TOUT   16             // outputs per thread (t0 = 16*tid)
#define MAX_B  96             // max experts per dst bucket
#define NF4    520            // f4 slots per buffer: 8 halo + 512 row

// Swizzle on float4 index: conflict-free for lane-stride-1 stores and
// lane-stride-4 window loads (verified bijection, all-distinct bank groups).
__device__ __forceinline__ int sw(int f4) { return f4 ^ ((f4 >> 2) & 7); }

// ---------------------------------------------------------------------------
// One block per dst row n. Phase A: single-pass scan of dst[] (cache-resident)
// with shuffle-scan, compact this row's experts (ascending e). Phase B: per
// expert, ping-pong smem staging (reg prefetch, 1 barrier/expert), scalar
// depthwise causal conv accumulated in registers. Phase C: out = x[n] + acc.
// ---------------------------------------------------------------------------
__global__ __launch_bounds__(TPB, 5)
void conv_route_kernel(const float* __restrict__ x,
                       const float* __restrict__ w,
                       const int*   __restrict__ src,
                       const int*   __restrict__ dst,
                       float*       __restrict__ out) {
    __shared__ __align__(128) float4 xsb[2][NF4];   // swizzled; [0..7]=causal halo
    __shared__ __align__(16)  float  wshb[2][K_TAPS];
    __shared__ int lst[MAX_B];
    __shared__ int wsum[4];

    const int tid  = threadIdx.x;
    const int lane = tid & 31;
    const int wid  = tid >> 5;
    const int n    = blockIdx.x;

    if (tid < 8) {                                   // halo (sw maps {0..7}->{0..7})
        xsb[0][tid] = make_float4(0.f, 0.f, 0.f, 0.f);
        xsb[1][tid] = make_float4(0.f, 0.f, 0.f, 0.f);
    }

    // ---------------- Phase A: routing discovery (single hot pass) --------
    const int4* d4 = (const int4*)dst;
    int cnt = 0;
#pragma unroll 8
    for (int c = 0; c < 32; ++c) {
        int4 v = d4[tid * 32 + c];
        cnt += (v.x == n) + (v.y == n) + (v.z == n) + (v.w == n);
    }
    int v = cnt;                                     // warp inclusive scan
#pragma unroll
    for (int o = 1; o < 32; o <<= 1) {
        int t = __shfl_up_sync(0xffffffffu, v, o);
        if (lane >= o) v += t;
    }
    if (lane == 31) wsum[wid] = v;
    __syncthreads();
    int base = 0, total = 0;
#pragma unroll
    for (int q = 0; q < 4; ++q) {
        int s = wsum[q];
        if (q < wid) base += s;
        total += s;
    }
    if (total > MAX_B) total = MAX_B;                // OOB guard (never in practice)
    if (cnt > 0) {                                   // only matching threads re-scan (L1 hits)
        int pos = base + v - cnt;
#pragma unroll 8
        for (int c = 0; c < 32; ++c) {
            int4 vv = d4[tid * 32 + c];
            int  e0 = tid * 128 + c * 4;
            if (vv.x == n && pos < MAX_B) lst[pos++] = e0;
            if (vv.y == n && pos < MAX_B) lst[pos++] = e0 + 1;
            if (vv.z == n && pos < MAX_B) lst[pos++] = e0 + 2;
            if (vv.w == n && pos < MAX_B) lst[pos++] = e0 + 3;
        }
    }
    __syncthreads();

    // ---------------- Phase B: conv + accumulate --------------------------
    float acc[TOUT];
#pragma unroll
    for (int j = 0; j < TOUT; ++j) acc[j] = 0.0f;

    float4 s0, s1, s2, s3;                           // prefetch registers
    float  wreg = 0.0f;
    if (0 < total) {
        int e = lst[0];
        const float4* row = (const float4*)(x + (size_t)src[e] * T_LEN);
        s0 = row[tid];
        s1 = row[tid + 128];
        s2 = row[tid + 256];
        s3 = row[tid + 384];
        if (tid < K_TAPS) wreg = w[e * K_TAPS + tid];
    }

    int p = 0;
    for (int i = 0; i < total; ++i, p ^= 1) {
        // Next-expert index resolved BEFORE the store phase (register copy).
        int e_next = (i + 1 < total) ? lst[i + 1] : -1;

        // Publish expert i into buf[p] (lane-stride-1 f4 stores, conflict-free).
        float4* xb = xsb[p];
        xb[sw(8 + tid)]       = s0;
        xb[sw(8 + tid + 128)] = s1;
        xb[sw(8 + tid + 256)] = s2;
        xb[sw(8 + tid + 384)] = s3;
        if (tid < K_TAPS) wshb[p][tid] = wreg;

        if (e_next >= 0) {                           // overlap: LDG expert i+1
            const float4* row = (const float4*)(x + (size_t)src[e_next] * T_LEN);
            s0 = row[tid];
            s1 = row[tid + 128];
            s2 = row[tid + 256];
            s3 = row[tid + 384];
            if (tid < K_TAPS) wreg = w[e_next * K_TAPS + tid];
        }

        __syncthreads();                             // single barrier per expert

        // Compute on buf[p]: thread owns t0=16*tid..t0+15; k in two 16-tap halves.
        const float4* xr = xsb[p];
        const float4* w4 = (const float4*)wshb[p];
#pragma unroll
        for (int h = 0; h < 2; ++h) {
            float xvv[32];
            const int cbase = 4 * (1 - h);
#pragma unroll
            for (int c = 0; c < 8; ++c) {
                float4 t = xr[sw(4 * tid + cbase + c)];
                xvv[4 * c + 0] = t.x; xvv[4 * c + 1] = t.y;
                xvv[4 * c + 2] = t.z; xvv[4 * c + 3] = t.w;
            }
#pragma unroll
            for (int kq = 0; kq < 4; ++kq) {
                float4 wv = w4[4 * h + kq];
#pragma unroll
                for (int j = 0; j < TOUT; ++j) acc[j] += xvv[16 + j - 4 * kq] * wv.x;
#pragma unroll
                for (int j = 0; j < TOUT; ++j) acc[j] += xvv[15 + j - 4 * kq] * wv.y;
#pragma unroll
                for (int j = 0; j < TOUT; ++j) acc[j] += xvv[14 + j - 4 * kq] * wv.z;
#pragma unroll
                for (int j = 0; j < TOUT; ++j) acc[j] += xvv[13 + j - 4 * kq] * wv.w;
            }
        }
    }

    // ---------------- Phase C: epilogue -----------------------------------
    const float4* xrow = (const float4*)(x + (size_t)n * T_LEN);
    float4*       orow = (float4*)(out + (size_t)n * T_LEN);
#pragma unroll
    for (int q = 0; q < 4; ++q) {
        float4 a = xrow[4 * tid + q];
        a.x += acc[4 * q + 0];
        a.y += acc[4 * q + 1];
        a.z += acc[4 * q + 2];
        a.w += acc[4 * q + 3];
        orow[4 * tid + q] = a;
    }
}

// ---------------------------------------------------------------------------
extern "C" void kernel_launch(void* const* d_in, const int* in_sizes, int n_in,
                              void* d_out, int out_size) {
    const float* x   = (const float*)d_in[0];
    const float* w   = (const float*)d_in[1];
    const int*   src = (const int*)d_in[2];
    const int*   dst = (const int*)d_in[3];
    float*       out = (float*)d_out;

    conv_route_kernel<<<N_ROWS, TPB>>>(x, w, src, dst, out);
}

// round 7
// speedup vs baseline: 1.2173x; 1.0145x over previous
#include <cuda_runtime.h>

#define N_ROWS 1024
#define T_LEN  2048
#define E_NUM  16384
#define K_TAPS 32
#define TPB    128            // threads per block
#define TOUT   16             // outputs per thread (t0 = 16*tid)
#define MAX_B  96             // max experts per dst bucket
#define NF4    520            // f4 slots per buffer: 8 halo + 512 row
#define GRID   740            // 148 SMs x 5 resident blocks

__device__ int g_ctr;         // work-stealing cursor (rows GRID..N_ROWS-1)

__global__ void init_ctr() { g_ctr = 0; }

// Swizzle on float4 index: conflict-free for lane-stride-1 stores and
// lane-stride-4 window loads (bijection, all-distinct bank groups).
__device__ __forceinline__ int sw(int f4) { return f4 ^ ((f4 >> 2) & 7); }

// ---------------------------------------------------------------------------
// Persistent blocks, one dst row at a time (static row = blockIdx.x, then
// steal). Per row: Phase A shuffle-scan of dst[] (cache-resident) -> expert
// list; Phase B ping-pong smem staging, 1 barrier/expert, scalar causal conv
// accumulated in registers (expert loop unrolled x2 so each copy has a
// compile-time buffer -> LDS [Roff+imm], no per-expert address ALU);
// Phase C out = x[n] + acc.
// ---------------------------------------------------------------------------
__global__ __launch_bounds__(TPB, 5)
void conv_route_kernel(const float* __restrict__ x,
                       const float* __restrict__ w,
                       const int*   __restrict__ src,
                       const int*   __restrict__ dst,
                       float*       __restrict__ out) {
    __shared__ __align__(128) float4 xsb[2][NF4];   // swizzled; [0..7] = causal halo
    __shared__ __align__(16)  float  wshb[2][K_TAPS];
    __shared__ int lst[MAX_B];
    __shared__ int wsum[4];
    __shared__ int sh_next;

    const int tid  = threadIdx.x;
    const int lane = tid & 31;
    const int wid  = tid >> 5;

    if (tid < 8) {                                   // halo, never overwritten
        xsb[0][tid] = make_float4(0.f, 0.f, 0.f, 0.f);
        xsb[1][tid] = make_float4(0.f, 0.f, 0.f, 0.f);
    }

    // Loop-invariant swizzled window offsets (float4 units) for this thread.
    int offs[12];
#pragma unroll
    for (int c = 0; c < 12; ++c) offs[c] = sw(4 * tid + c);

    const int4* d4 = (const int4*)dst;

    int row = blockIdx.x;
    while (row < N_ROWS) {
        const int n = row;

        // ---------------- Phase A: routing discovery ----------------------
        int cnt = 0;
#pragma unroll 8
        for (int c = 0; c < 32; ++c) {
            int4 v = d4[tid * 32 + c];
            cnt += (v.x == n) + (v.y == n) + (v.z == n) + (v.w == n);
        }
        int v = cnt;                                 // warp inclusive scan
#pragma unroll
        for (int o = 1; o < 32; o <<= 1) {
            int t = __shfl_up_sync(0xffffffffu, v, o);
            if (lane >= o) v += t;
        }
        if (lane == 31) wsum[wid] = v;
        __syncthreads();
        int base = 0, total = 0;
#pragma unroll
        for (int q = 0; q < 4; ++q) {
            int s = wsum[q];
            if (q < wid) base += s;
            total += s;
        }
        if (total > MAX_B) total = MAX_B;            // OOB guard
        if (cnt > 0) {                               // matching threads only (L1 hits)
            int pos = base + v - cnt;
#pragma unroll 8
            for (int c = 0; c < 32; ++c) {
                int4 vv = d4[tid * 32 + c];
                int  e0 = tid * 128 + c * 4;
                if (vv.x == n && pos < MAX_B) lst[pos++] = e0;
                if (vv.y == n && pos < MAX_B) lst[pos++] = e0 + 1;
                if (vv.z == n && pos < MAX_B) lst[pos++] = e0 + 2;
                if (vv.w == n && pos < MAX_B) lst[pos++] = e0 + 3;
            }
        }
        __syncthreads();

        // ---------------- Phase B: conv + accumulate ----------------------
        float acc[TOUT];
#pragma unroll
        for (int j = 0; j < TOUT; ++j) acc[j] = 0.0f;

        float4 s0, s1, s2, s3;
        float  wreg = 0.0f;
        if (0 < total) {
            int e = lst[0];
            const float4* r = (const float4*)(x + (size_t)src[e] * T_LEN);
            s0 = r[tid]; s1 = r[tid + 128]; s2 = r[tid + 256]; s3 = r[tid + 384];
            if (tid < K_TAPS) wreg = w[e * K_TAPS + tid];
        }

#define STAGE_AND_COMPUTE(P)                                                   \
        {                                                                      \
            float4* xb = xsb[P];                                               \
            xb[sw(8 + tid)]       = s0;                                        \
            xb[sw(8 + tid + 128)] = s1;                                        \
            xb[sw(8 + tid + 256)] = s2;                                        \
            xb[sw(8 + tid + 384)] = s3;                                        \
            if (tid < K_TAPS) wshb[P][tid] = wreg;                             \
            if (i + 1 < total) {                                               \
                int e = lst[i + 1];                                            \
                const float4* r = (const float4*)(x + (size_t)src[e] * T_LEN); \
                s0 = r[tid]; s1 = r[tid + 128];                                \
                s2 = r[tid + 256]; s3 = r[tid + 384];                          \
                if (tid < K_TAPS) wreg = w[e * K_TAPS + tid];                  \
            }                                                                  \
            __syncthreads();                                                   \
            const float4* xr = xsb[P];                                         \
            const float4* w4 = (const float4*)wshb[P];                         \
            _Pragma("unroll")                                                  \
            for (int h = 0; h < 2; ++h) {                                      \
                float xvv[32];                                                 \
                const int cb = 4 * (1 - h);                                    \
                _Pragma("unroll")                                              \
                for (int c = 0; c < 8; ++c) {                                  \
                    float4 t = xr[offs[cb + c]];                               \
                    xvv[4 * c + 0] = t.x; xvv[4 * c + 1] = t.y;                \
                    xvv[4 * c + 2] = t.z; xvv[4 * c + 3] = t.w;                \
                }                                                              \
                _Pragma("unroll")                                              \
                for (int kq = 0; kq < 4; ++kq) {                               \
                    float4 wv = w4[4 * h + kq];                                \
                    _Pragma("unroll")                                          \
                    for (int j = 0; j < TOUT; ++j)                             \
                        acc[j] += xvv[16 + j - 4 * kq] * wv.x;                 \
                    _Pragma("unroll")                                          \
                    for (int j = 0; j < TOUT; ++j)                             \
                        acc[j] += xvv[15 + j - 4 * kq] * wv.y;                 \
                    _Pragma("unroll")                                          \
                    for (int j = 0; j < TOUT; ++j)                             \
                        acc[j] += xvv[14 + j - 4 * kq] * wv.z;                 \
                    _Pragma("unroll")                                          \
                    for (int j = 0; j < TOUT; ++j)                             \
                        acc[j] += xvv[13 + j - 4 * kq] * wv.w;                 \
                }                                                              \
            }                                                                  \
        }

        int i = 0;
        while (i < total) {
            STAGE_AND_COMPUTE(0)
            ++i;
            if (i >= total) break;
            STAGE_AND_COMPUTE(1)
            ++i;
        }
#undef STAGE_AND_COMPUTE

        // ---------------- Phase C: epilogue -------------------------------
        const float4* xrow = (const float4*)(x + (size_t)n * T_LEN);
        float4*       orow = (float4*)(out + (size_t)n * T_LEN);
#pragma unroll
        for (int q = 0; q < 4; ++q) {
            float4 a = xrow[4 * tid + q];
            a.x += acc[4 * q + 0];
            a.y += acc[4 * q + 1];
            a.z += acc[4 * q + 2];
            a.w += acc[4 * q + 3];
            orow[4 * tid + q] = a;
        }

        // ---------------- Claim next row ----------------------------------
        if (tid == 0) sh_next = GRID + atomicAdd(&g_ctr, 1);
        __syncthreads();
        row = sh_next;
        __syncthreads();          // sh_next consumed before next row's reuse
    }
}

// ---------------------------------------------------------------------------
extern "C" void kernel_launch(void* const* d_in, const int* in_sizes, int n_in,
                              void* d_out, int out_size) {
    const float* x   = (const float*)d_in[0];
    const float* w   = (const float*)d_in[1];
    const int*   src = (const int*)d_in[2];
    const int*   dst = (const int*)d_in[3];
    float*       out = (float*)d_out;

    init_ctr<<<1, 1>>>();
    conv_route_kernel<<<GRID, TPB>>>(x, w, src, dst, out);
}

// round 9
// speedup vs baseline: 1.2177x; 1.0004x over previous
#include <cuda_runtime.h>

#define N_ROWS 1024
#define T_LEN  2048
#define E_NUM  16384
#define K_TAPS 32
#define TPB    128            // threads per block
#define TOUT   16             // outputs per thread (t0 = 16*tid)
#define MAX_B  96             // max experts per dst bucket
#define NF4    520            // f4 slots per buffer: 8 halo + 512 row
#define GRID   592            // 148 SMs x 4 resident blocks

__device__ int g_ctr;         // work-stealing cursor (rows GRID..N_ROWS-1)

__global__ void init_ctr() { g_ctr = 0; }

// Swizzle on float4 index: conflict-free for lane-stride-1 stores and
// lane-stride-4 window loads (bijection, all-distinct bank groups).
__device__ __forceinline__ int sw(int f4) { return f4 ^ ((f4 >> 2) & 7); }

__device__ __forceinline__ float f4c(const float4& v, int d) {
    return d == 0 ? v.x : d == 1 ? v.y : d == 2 ? v.z : v.w;  // d compile-time
}

// ---------------------------------------------------------------------------
// Persistent blocks, one dst row at a time. Phase A: shuffle-scan of dst[]
// (cache-resident) -> expert list. Phase B: ping-pong smem staging, 1 barrier
// per expert; ALL 32 weights in registers; window streamed one float4 at a
// time with the WEIGHT index shifted per output (register-direct FMAs, no
// data-shift copies). Phase C: out = x[n] + acc.
// ---------------------------------------------------------------------------
__global__ __launch_bounds__(TPB, 4)
void conv_route_kernel(const float* __restrict__ x,
                       const float* __restrict__ w,
                       const int*   __restrict__ src,
                       const int*   __restrict__ dst,
                       float*       __restrict__ out) {
    __shared__ __align__(128) float4 xsb[2][NF4];   // swizzled; [0..7] = causal halo
    __shared__ __align__(16)  float  wshb[2][K_TAPS];
    __shared__ int lst[MAX_B];
    __shared__ int wsum[4];
    __shared__ int sh_next;

    const int tid  = threadIdx.x;
    const int lane = tid & 31;
    const int wid  = tid >> 5;

    if (tid < 8) {                                   // halo, never overwritten
        xsb[0][tid] = make_float4(0.f, 0.f, 0.f, 0.f);
        xsb[1][tid] = make_float4(0.f, 0.f, 0.f, 0.f);
    }

    // Loop-invariant swizzled offsets (float4 units): 12 window loads + 4 stores.
    int offs[12];
#pragma unroll
    for (int c = 0; c < 12; ++c) offs[c] = sw(4 * tid + c);
    const int so0 = sw(8 + tid),       so1 = sw(8 + tid + 128);
    const int so2 = sw(8 + tid + 256), so3 = sw(8 + tid + 384);

    const int4* d4 = (const int4*)dst;

    int row = blockIdx.x;
    while (row < N_ROWS) {
        const int n = row;

        // ---------------- Phase A: routing discovery ----------------------
        int cnt = 0;
#pragma unroll 8
        for (int c = 0; c < 32; ++c) {
            int4 v = d4[tid * 32 + c];
            cnt += (v.x == n) + (v.y == n) + (v.z == n) + (v.w == n);
        }
        int v = cnt;                                 // warp inclusive scan
#pragma unroll
        for (int o = 1; o < 32; o <<= 1) {
            int t = __shfl_up_sync(0xffffffffu, v, o);
            if (lane >= o) v += t;
        }
        if (lane == 31) wsum[wid] = v;
        __syncthreads();
        int base = 0, total = 0;
#pragma unroll
        for (int q = 0; q < 4; ++q) {
            int s = wsum[q];
            if (q < wid) base += s;
            total += s;
        }
        if (total > MAX_B) total = MAX_B;            // OOB guard
        if (cnt > 0) {                               // matching threads only (L1 hits)
            int pos = base + v - cnt;
#pragma unroll 8
            for (int c = 0; c < 32; ++c) {
                int4 vv = d4[tid * 32 + c];
                int  e0 = tid * 128 + c * 4;
                if (vv.x == n && pos < MAX_B) lst[pos++] = e0;
                if (vv.y == n && pos < MAX_B) lst[pos++] = e0 + 1;
                if (vv.z == n && pos < MAX_B) lst[pos++] = e0 + 2;
                if (vv.w == n && pos < MAX_B) lst[pos++] = e0 + 3;
            }
        }
        __syncthreads();

        // ---------------- Phase B: conv + accumulate ----------------------
        float acc[TOUT];
#pragma unroll
        for (int j = 0; j < TOUT; ++j) acc[j] = 0.0f;

        float4 s0, s1, s2, s3;
        float  wreg = 0.0f;
        if (0 < total) {
            int e = lst[0];
            const float4* r = (const float4*)(x + (size_t)src[e] * T_LEN);
            s0 = r[tid]; s1 = r[tid + 128]; s2 = r[tid + 256]; s3 = r[tid + 384];
            if (tid < K_TAPS) wreg = w[e * K_TAPS + tid];
        }

#define STAGE_AND_COMPUTE(P)                                                   \
        {                                                                      \
            float4* xb = xsb[P];                                               \
            xb[so0] = s0; xb[so1] = s1; xb[so2] = s2; xb[so3] = s3;            \
            if (tid < K_TAPS) wshb[P][tid] = wreg;                             \
            if (i + 1 < total) {                                               \
                int e = lst[i + 1];                                            \
                const float4* r = (const float4*)(x + (size_t)src[e] * T_LEN); \
                s0 = r[tid]; s1 = r[tid + 128];                                \
                s2 = r[tid + 256]; s3 = r[tid + 384];                          \
                if (tid < K_TAPS) wreg = w[e * K_TAPS + tid];                  \
            }                                                                  \
            __syncthreads();                                                   \
            const float4* xr = xsb[P];                                         \
            const float4* w4 = (const float4*)wshb[P];                         \
            float wf[K_TAPS];                                                  \
            _Pragma("unroll")                                                  \
            for (int q = 0; q < 8; ++q) {                                      \
                float4 wv = w4[q];                                             \
                wf[4 * q] = wv.x; wf[4 * q + 1] = wv.y;                        \
                wf[4 * q + 2] = wv.z; wf[4 * q + 3] = wv.w;                    \
            }                                                                  \
            _Pragma("unroll")                                                  \
            for (int c = 0; c < 12; ++c) {                                     \
                float4 V = xr[offs[c]];                                        \
                _Pragma("unroll")                                              \
                for (int d = 0; d < 4; ++d) {                                  \
                    const int u  = 4 * c + d;                                  \
                    const float xv = f4c(V, d);                                \
                    const int jlo = (u > 32) ? (u - 32) : 0;                   \
                    const int jhi = (u - 1 < 15) ? (u - 1) : 15;               \
                    _Pragma("unroll")                                          \
                    for (int j = jlo; j <= jhi; ++j)                           \
                        acc[j] += xv * wf[32 + j - u];                         \
                }                                                              \
            }                                                                  \
        }

        int i = 0;
        while (i < total) {
            STAGE_AND_COMPUTE(0)
            ++i;
            if (i >= total) break;
            STAGE_AND_COMPUTE(1)
            ++i;
        }
#undef STAGE_AND_COMPUTE

        // ---------------- Phase C: epilogue -------------------------------
        const float4* xrow = (const float4*)(x + (size_t)n * T_LEN);
        float4*       orow = (float4*)(out + (size_t)n * T_LEN);
#pragma unroll
        for (int q = 0; q < 4; ++q) {
            float4 a = xrow[4 * tid + q];
            a.x += acc[4 * q + 0];
            a.y += acc[4 * q + 1];
            a.z += acc[4 * q + 2];
            a.w += acc[4 * q + 3];
            orow[4 * tid + q] = a;
        }

        // ---------------- Claim next row ----------------------------------
        if (tid == 0) sh_next = GRID + atomicAdd(&g_ctr, 1);
        __syncthreads();
        row = sh_next;
        __syncthreads();          // sh_next consumed before reuse
    }
}

// ---------------------------------------------------------------------------
extern "C" void kernel_launch(void* const* d_in, const int* in_sizes, int n_in,
                              void* d_out, int out_size) {
    const float* x   = (const float*)d_in[0];
    const float* w   = (const float*)d_in[1];
    const int*   src = (const int*)d_in[2];
    const int*   dst = (const int*)d_in[3];
    float*       out = (float*)d_out;

    init_ctr<<<1, 1>>>();
    conv_route_kernel<<<GRID, TPB>>>(x, w, src, dst, out);
}

// round 10
// speedup vs baseline: 1.2490x; 1.0257x over previous
#include <cuda_runtime.h>

#define N_ROWS 1024
#define T_LEN  2048
#define E_NUM  16384
#define K_TAPS 32
#define TPB    128
#define TOUT   16             // outputs per thread (t0 = 16*tid)
#define MAX_B  96             // max experts per dst bucket
#define NF4    520            // f4 slots per row buffer: 8 halo + 512 row
#define GRID   592            // 148 SMs x 4 resident blocks

__device__ int g_ctr;                       // work-steal cursor
__device__ int g_cnt[N_ROWS];               // experts per dst row
__device__ int g_lst[N_ROWS][MAX_B];        // expert ids, ascending

__global__ void init_ctr() { g_ctr = 0; }

// Swizzle on float4 index: conflict-free for lane-stride-1 stores and
// lane-stride-4 window loads (bijection, all-distinct bank groups).
__device__ __forceinline__ int sw(int f4) { return f4 ^ ((f4 >> 2) & 7); }

__device__ __forceinline__ float f4c(const float4& v, int d) {
    return d == 0 ? v.x : d == 1 ? v.y : d == 2 ? v.z : v.w;  // d compile-time
}

// ---------------------------------------------------------------------------
// Kernel 1: routing discovery, one block per dst row (L2-BW bound, ~6us).
// ---------------------------------------------------------------------------
__global__ __launch_bounds__(TPB)
void build_lists(const int* __restrict__ dst) {
    __shared__ int wsum[4];
    const int tid  = threadIdx.x;
    const int lane = tid & 31;
    const int wid  = tid >> 5;
    const int n    = blockIdx.x;

    const int4* d4 = (const int4*)dst;
    int cnt = 0;
#pragma unroll 8
    for (int c = 0; c < 32; ++c) {
        int4 v = d4[tid * 32 + c];
        cnt += (v.x == n) + (v.y == n) + (v.z == n) + (v.w == n);
    }
    int v = cnt;
#pragma unroll
    for (int o = 1; o < 32; o <<= 1) {
        int t = __shfl_up_sync(0xffffffffu, v, o);
        if (lane >= o) v += t;
    }
    if (lane == 31) wsum[wid] = v;
    __syncthreads();
    int base = 0, total = 0;
#pragma unroll
    for (int q = 0; q < 4; ++q) {
        int s = wsum[q];
        if (q < wid) base += s;
        total += s;
    }
    if (total > MAX_B) total = MAX_B;
    if (cnt > 0) {
        int pos = base + v - cnt;
#pragma unroll 8
        for (int c = 0; c < 32; ++c) {
            int4 vv = d4[tid * 32 + c];
            int  e0 = tid * 128 + c * 4;
            if (vv.x == n && pos < MAX_B) g_lst[n][pos++] = e0;
            if (vv.y == n && pos < MAX_B) g_lst[n][pos++] = e0 + 1;
            if (vv.z == n && pos < MAX_B) g_lst[n][pos++] = e0 + 2;
            if (vv.w == n && pos < MAX_B) g_lst[n][pos++] = e0 + 3;
        }
    }
    if (tid == 0) g_cnt[n] = total;
}

// ---------------------------------------------------------------------------
// Kernel 2: persistent conv blocks. Per row: copy list to smem; process
// experts in PAIRS (4 row buffers, ONE barrier per pair, ~1024 FMAs between
// syncs); weight-shift register FMAs; epilogue out = x[n] + acc.
// ---------------------------------------------------------------------------
__global__ __launch_bounds__(TPB, 4)
void conv_route_kernel(const float* __restrict__ x,
                       const float* __restrict__ w,
                       const int*   __restrict__ src,
                       float*       __restrict__ out) {
    __shared__ __align__(128) float4 xsb[4][NF4];   // swizzled; [0..7] = halo
    __shared__ __align__(16)  float  wshb[4][K_TAPS];
    __shared__ int slst[MAX_B];
    __shared__ int sh_next;

    const int tid = threadIdx.x;

    if (tid < 8) {
#pragma unroll
        for (int b = 0; b < 4; ++b)
            xsb[b][tid] = make_float4(0.f, 0.f, 0.f, 0.f);
    }

    int offs[12];
#pragma unroll
    for (int c = 0; c < 12; ++c) offs[c] = sw(4 * tid + c);
    const int so0 = sw(8 + tid),       so1 = sw(8 + tid + 128);
    const int so2 = sw(8 + tid + 256), so3 = sw(8 + tid + 384);

    int row = blockIdx.x;
    while (row < N_ROWS) {
        const int n   = row;
        const int cnt = g_cnt[n];

        if (tid < cnt) slst[tid] = g_lst[n][tid];
        __syncthreads();

        float acc[TOUT];
#pragma unroll
        for (int j = 0; j < TOUT; ++j) acc[j] = 0.0f;

        // Pair prefetch registers (zero-init: last odd pair stages r1 garbage-free).
        float4 r0a = {}, r0b = {}, r0c = {}, r0d = {};
        float4 r1a = {}, r1b = {}, r1c = {}, r1d = {};
        float  w0 = 0.f, w1 = 0.f;
        if (cnt > 0) {
            int e = slst[0];
            const float4* r = (const float4*)(x + (size_t)src[e] * T_LEN);
            r0a = r[tid]; r0b = r[tid + 128]; r0c = r[tid + 256]; r0d = r[tid + 384];
            if (tid < K_TAPS) w0 = w[e * K_TAPS + tid];
        }
        if (cnt > 1) {
            int e = slst[1];
            const float4* r = (const float4*)(x + (size_t)src[e] * T_LEN);
            r1a = r[tid]; r1b = r[tid + 128]; r1c = r[tid + 256]; r1d = r[tid + 384];
            if (tid < K_TAPS) w1 = w[e * K_TAPS + tid];
        }

#define COMPUTE_EXPERT(B)                                                      \
        {                                                                      \
            const float4* xr = xsb[B];                                         \
            const float4* w4 = (const float4*)wshb[B];                         \
            float wf[K_TAPS];                                                  \
            _Pragma("unroll")                                                  \
            for (int q = 0; q < 8; ++q) {                                      \
                float4 wv = w4[q];                                             \
                wf[4 * q] = wv.x; wf[4 * q + 1] = wv.y;                        \
                wf[4 * q + 2] = wv.z; wf[4 * q + 3] = wv.w;                    \
            }                                                                  \
            _Pragma("unroll")                                                  \
            for (int c = 0; c < 12; ++c) {                                     \
                float4 V = xr[offs[c]];                                        \
                _Pragma("unroll")                                              \
                for (int d = 0; d < 4; ++d) {                                  \
                    const int u  = 4 * c + d;                                  \
                    const float xv = f4c(V, d);                                \
                    const int jlo = (u > 32) ? (u - 32) : 0;                   \
                    const int jhi = (u - 1 < 15) ? (u - 1) : 15;               \
                    _Pragma("unroll")                                          \
                    for (int j = jlo; j <= jhi; ++j)                           \
                        acc[j] += xv * wf[32 + j - u];                         \
                }                                                              \
            }                                                                  \
        }

#define STAGE_PAIR(P)                                                          \
        {                                                                      \
            float4* b0 = xsb[2 * (P)];                                         \
            float4* b1 = xsb[2 * (P) + 1];                                     \
            b0[so0] = r0a; b0[so1] = r0b; b0[so2] = r0c; b0[so3] = r0d;        \
            b1[so0] = r1a; b1[so1] = r1b; b1[so2] = r1c; b1[so3] = r1d;        \
            if (tid < K_TAPS) {                                                \
                wshb[2 * (P)][tid]     = w0;                                   \
                wshb[2 * (P) + 1][tid] = w1;                                   \
            }                                                                  \
            if (2 * q + 2 < cnt) {                                             \
                int e = slst[2 * q + 2];                                       \
                const float4* r = (const float4*)(x + (size_t)src[e] * T_LEN); \
                r0a = r[tid]; r0b = r[tid + 128];                              \
                r0c = r[tid + 256]; r0d = r[tid + 384];                        \
                if (tid < K_TAPS) w0 = w[e * K_TAPS + tid];                    \
            }                                                                  \
            if (2 * q + 3 < cnt) {                                             \
                int e = slst[2 * q + 3];                                       \
                const float4* r = (const float4*)(x + (size_t)src[e] * T_LEN); \
                r1a = r[tid]; r1b = r[tid + 128];                              \
                r1c = r[tid + 256]; r1d = r[tid + 384];                        \
                if (tid < K_TAPS) w1 = w[e * K_TAPS + tid];                    \
            } else { w1 = 0.f; }                                               \
            __syncthreads();                                                   \
            COMPUTE_EXPERT(2 * (P))                                            \
            if (2 * q + 1 < cnt) COMPUTE_EXPERT(2 * (P) + 1)                   \
        }

        const int npairs = (cnt + 1) >> 1;
        int q = 0;
        while (q < npairs) {
            STAGE_PAIR(0)
            ++q;
            if (q >= npairs) break;
            STAGE_PAIR(1)
            ++q;
        }
#undef STAGE_PAIR
#undef COMPUTE_EXPERT

        // Epilogue
        const float4* xrow = (const float4*)(x + (size_t)n * T_LEN);
        float4*       orow = (float4*)(out + (size_t)n * T_LEN);
#pragma unroll
        for (int p2 = 0; p2 < 4; ++p2) {
            float4 a = xrow[4 * tid + p2];
            a.x += acc[4 * p2 + 0];
            a.y += acc[4 * p2 + 1];
            a.z += acc[4 * p2 + 2];
            a.w += acc[4 * p2 + 3];
            orow[4 * tid + p2] = a;
        }

        if (tid == 0) sh_next = GRID + atomicAdd(&g_ctr, 1);
        __syncthreads();
        row = sh_next;
        __syncthreads();
    }
}

// ---------------------------------------------------------------------------
extern "C" void kernel_launch(void* const* d_in, const int* in_sizes, int n_in,
                              void* d_out, int out_size) {
    const float* x   = (const float*)d_in[0];
    const float* w   = (const float*)d_in[1];
    const int*   src = (const int*)d_in[2];
    const int*   dst = (const int*)d_in[3];
    float*       out = (float*)d_out;

    init_ctr<<<1, 1>>>();
    build_lists<<<N_ROWS, TPB>>>(dst);
    conv_route_kernel<<<GRID, TPB>>>(x, w, src, out);
}

// round 12
// speedup vs baseline: 1.3291x; 1.0642x over previous
#include <cuda_runtime.h>

#define N_ROWS 1024
#define T_LEN  2048
#define E_NUM  16384
#define K_TAPS 32
#define TPB    128
#define TOUT   16             // outputs per thread (t0 = 16*tid)
#define MAX_B  96             // max experts per dst bucket
#define NF4    520            // f4 slots per row buffer: 8 halo + 512 row
#define GRID   888            // 148 SMs x 6 resident blocks

__device__ int g_ctr;                       // work-steal cursor
__device__ int g_cnt[N_ROWS];               // experts per dst row
__device__ int g_lst[N_ROWS][MAX_B];        // expert ids, ascending

// Swizzle on float4 index: conflict-free for lane-stride-1 fills and
// lane-stride-4 window loads (bijection, all-distinct bank groups).
__device__ __forceinline__ int sw(int f4) { return f4 ^ ((f4 >> 2) & 7); }

__device__ __forceinline__ float f4c(const float4& v, int d) {
    return d == 0 ? v.x : d == 1 ? v.y : d == 2 ? v.z : v.w;  // d compile-time
}

__device__ __forceinline__ void cp16(void* s, const void* g) {
    unsigned sa = (unsigned)__cvta_generic_to_shared(s);
    asm volatile("cp.async.cg.shared.global [%0], [%1], 16;" :: "r"(sa), "l"(g));
}
#define CP_COMMIT()  asm volatile("cp.async.commit_group;")
#define CP_WAIT1()   asm volatile("cp.async.wait_group 1;")
#define CP_WAIT0()   asm volatile("cp.async.wait_group 0;")

// ---------------------------------------------------------------------------
// Kernel 1: routing discovery, one block per dst row (L2-BW bound).
// Also resets the work-steal cursor (kernels serialize on the stream).
// ---------------------------------------------------------------------------
__global__ __launch_bounds__(TPB)
void build_lists(const int* __restrict__ dst) {
    __shared__ int wsum[4];
    const int tid  = threadIdx.x;
    const int lane = tid & 31;
    const int wid  = tid >> 5;
    const int n    = blockIdx.x;

    if (n == 0 && tid == 0) g_ctr = 0;

    const int4* d4 = (const int4*)dst;
    int cnt = 0;
#pragma unroll 8
    for (int c = 0; c < 32; ++c) {
        int4 v = d4[tid * 32 + c];
        cnt += (v.x == n) + (v.y == n) + (v.z == n) + (v.w == n);
    }
    int v = cnt;
#pragma unroll
    for (int o = 1; o < 32; o <<= 1) {
        int t = __shfl_up_sync(0xffffffffu, v, o);
        if (lane >= o) v += t;
    }
    if (lane == 31) wsum[wid] = v;
    __syncthreads();
    int base = 0, total = 0;
#pragma unroll
    for (int q = 0; q < 4; ++q) {
        int s = wsum[q];
        if (q < wid) base += s;
        total += s;
    }
    if (total > MAX_B) total = MAX_B;
    if (cnt > 0) {
        int pos = base + v - cnt;
#pragma unroll 8
        for (int c = 0; c < 32; ++c) {
            int4 vv = d4[tid * 32 + c];
            int  e0 = tid * 128 + c * 4;
            if (vv.x == n && pos < MAX_B) g_lst[n][pos++] = e0;
            if (vv.y == n && pos < MAX_B) g_lst[n][pos++] = e0 + 1;
            if (vv.z == n && pos < MAX_B) g_lst[n][pos++] = e0 + 2;
            if (vv.w == n && pos < MAX_B) g_lst[n][pos++] = e0 + 3;
        }
    }
    if (tid == 0) g_cnt[n] = total;
}

// ---------------------------------------------------------------------------
// Kernel 2: persistent conv blocks, 6/SM. Per row: 3-stage cp.async ring of
// expert rows (gmem->smem, no reg staging), 1 barrier per expert, weight-shift
// register FMAs (all 32 weights in regs), epilogue out = x[n] + acc.
// Last expert of a row uses wait_group 0 (a lone pending group is NOT
// completed by wait_group 1) — also drains the pipe before the next row.
// ---------------------------------------------------------------------------
__global__ __launch_bounds__(TPB, 6)
void conv_route_kernel(const float* __restrict__ x,
                       const float* __restrict__ w,
                       const int*   __restrict__ src,
                       float*       __restrict__ out) {
    __shared__ __align__(128) float4 xsb[3][NF4];   // swizzled; [0..7] = halo
    __shared__ __align__(16)  float  wshb[3][K_TAPS];
    __shared__ int slst[MAX_B];
    __shared__ int sh_next;

    const int tid = threadIdx.x;

    if (tid < 8) {                                   // halo, never overwritten
#pragma unroll
        for (int b = 0; b < 3; ++b)
            xsb[b][tid] = make_float4(0.f, 0.f, 0.f, 0.f);
    }

    int offs[12];
#pragma unroll
    for (int c = 0; c < 12; ++c) offs[c] = sw(4 * tid + c);
    const int so0 = sw(8 + tid),       so1 = sw(8 + tid + 128);
    const int so2 = sw(8 + tid + 256), so3 = sw(8 + tid + 384);

    // Issue one expert's row + weights into ring buffer b via cp.async.
#define ISSUE(EIDX, B)                                                         \
    {                                                                          \
        int e = slst[EIDX];                                                    \
        const float* r = x + (size_t)src[e] * T_LEN;                           \
        cp16(&xsb[B][so0], r + 4 * tid);                                       \
        cp16(&xsb[B][so1], r + 4 * (tid + 128));                               \
        cp16(&xsb[B][so2], r + 4 * (tid + 256));                               \
        cp16(&xsb[B][so3], r + 4 * (tid + 384));                               \
        if (tid < 8) cp16(&wshb[B][4 * tid], w + e * K_TAPS + 4 * tid);        \
        CP_COMMIT();                                                           \
    }

#define COMPUTE(B)                                                             \
    {                                                                          \
        const float4* xr = xsb[B];                                             \
        const float4* w4 = (const float4*)wshb[B];                             \
        float wf[K_TAPS];                                                      \
        _Pragma("unroll")                                                      \
        for (int q = 0; q < 8; ++q) {                                          \
            float4 wv = w4[q];                                                 \
            wf[4 * q] = wv.x; wf[4 * q + 1] = wv.y;                            \
            wf[4 * q + 2] = wv.z; wf[4 * q + 3] = wv.w;                        \
        }                                                                      \
        _Pragma("unroll")                                                      \
        for (int c = 0; c < 12; ++c) {                                         \
            float4 V = xr[offs[c]];                                            \
            _Pragma("unroll")                                                  \
            for (int d = 0; d < 4; ++d) {                                      \
                const int u  = 4 * c + d;                                      \
                const float xv = f4c(V, d);                                    \
                const int jlo = (u > 32) ? (u - 32) : 0;                       \
                const int jhi = (u - 1 < 15) ? (u - 1) : 15;                   \
                _Pragma("unroll")                                              \
                for (int j = jlo; j <= jhi; ++j)                               \
                    acc[j] += xv * wf[32 + j - u];                             \
            }                                                                  \
        }                                                                      \
    }

    // STEP(B): expert i lives in buffer B; prefetch expert i+2 into (B+2)%3.
    // If i is the LAST expert, only its group can be pending -> wait_group 0.
#define STEP(B)                                                                \
    {                                                                          \
        if (i + 1 < cnt) { CP_WAIT1(); } else { CP_WAIT0(); }                  \
        __syncthreads();                                                       \
        if (i + 2 < cnt) ISSUE(i + 2, (B + 2) % 3)                             \
        COMPUTE(B)                                                             \
    }

    int row = blockIdx.x;
    while (row < N_ROWS) {
        const int n   = row;
        const int cnt = g_cnt[n];

        if (tid < cnt) slst[tid] = g_lst[n][tid];
        __syncthreads();

        float acc[TOUT];
#pragma unroll
        for (int j = 0; j < TOUT; ++j) acc[j] = 0.0f;

        if (cnt > 0) ISSUE(0, 0)
        if (cnt > 1) ISSUE(1, 1)

        int i = 0;
        while (i < cnt) {
            STEP(0) ++i; if (i >= cnt) break;
            STEP(1) ++i; if (i >= cnt) break;
            STEP(2) ++i;
        }

        // Epilogue: out[n] = x[n] + acc
        const float4* xrow = (const float4*)(x + (size_t)n * T_LEN);
        float4*       orow = (float4*)(out + (size_t)n * T_LEN);
#pragma unroll
        for (int p2 = 0; p2 < 4; ++p2) {
            float4 a = xrow[4 * tid + p2];
            a.x += acc[4 * p2 + 0];
            a.y += acc[4 * p2 + 1];
            a.z += acc[4 * p2 + 2];
            a.w += acc[4 * p2 + 3];
            orow[4 * tid + p2] = a;
        }

        if (tid == 0) sh_next = GRID + atomicAdd(&g_ctr, 1);
        __syncthreads();
        row = sh_next;
        __syncthreads();
    }
#undef STEP
#undef COMPUTE
#undef ISSUE
}

// ---------------------------------------------------------------------------
extern "C" void kernel_launch(void* const* d_in, const int* in_sizes, int n_in,
                              void* d_out, int out_size) {
    const float* x   = (const float*)d_in[0];
    const float* w   = (const float*)d_in[1];
    const int*   src = (const int*)d_in[2];
    const int*   dst = (const int*)d_in[3];
    float*       out = (float*)d_out;

    build_lists<<<N_ROWS, TPB>>>(dst);
    conv_route_kernel<<<GRID, TPB>>>(x, w, src, out);
}

// round 13
// speedup vs baseline: 1.3446x; 1.0116x over previous
#include <cuda_runtime.h>

#define N_ROWS 1024
#define T_LEN  2048
#define E_NUM  16384
#define K_TAPS 32
#define TPB    128
#define TOUT   16             // outputs per thread (t0 = 16*tid)
#define MAX_B  96             // max experts per dst bucket
#define NF4    520            // f4 slots per row buffer: 8 halo + 512 row
#define GRID   888            // 148 SMs x 6 resident blocks

__device__ int g_ctr;                       // work-steal cursor
__device__ int g_cnt[N_ROWS];               // experts per dst row (zero-init; conv re-zeros)
__device__ int g_lst[N_ROWS][MAX_B];        // expert ids (unordered; conv sorts)

// Swizzle on float4 index: conflict-free for lane-stride-1 fills and
// lane-stride-4 window loads (bijection, all-distinct bank groups).
__device__ __forceinline__ int sw(int f4) { return f4 ^ ((f4 >> 2) & 7); }

__device__ __forceinline__ float f4c(const float4& v, int d) {
    return d == 0 ? v.x : d == 1 ? v.y : d == 2 ? v.z : v.w;  // d compile-time
}

__device__ __forceinline__ void cp16(void* s, const void* g) {
    unsigned sa = (unsigned)__cvta_generic_to_shared(s);
    asm volatile("cp.async.cg.shared.global [%0], [%1], 16;" :: "r"(sa), "l"(g));
}
#define CP_COMMIT()  asm volatile("cp.async.commit_group;")
#define CP_WAIT1()   asm volatile("cp.async.wait_group 1;")
#define CP_WAIT0()   asm volatile("cp.async.wait_group 0;")

// ---------------------------------------------------------------------------
// Kernel 1: O(E) scatter. One thread per expert. Order within a row is
// nondeterministic here; the conv kernel sorts each row's short list.
// Also resets the work-steal cursor. Relies on g_cnt == 0 on entry
// (true at module load; conv re-zeros each row after consuming it).
// ---------------------------------------------------------------------------
__global__ __launch_bounds__(256)
void scatter_experts(const int* __restrict__ dst) {
    int e = blockIdx.x * 256 + threadIdx.x;
    if (e == 0) g_ctr = 0;
    if (e < E_NUM) {
        int v = dst[e];
        int pos = atomicAdd(&g_cnt[v], 1);
        if (pos < MAX_B) g_lst[v][pos] = e;
    }
}

// ---------------------------------------------------------------------------
// Kernel 2: persistent conv blocks, 6/SM. Per row: copy + bitonic-sort the
// expert list (determinism), zero g_cnt[n] for the next graph replay, then
// 3-stage cp.async ring of expert rows, 1 barrier per expert, weight-shift
// register FMAs, epilogue out = x[n] + acc.
// ---------------------------------------------------------------------------
__global__ __launch_bounds__(TPB, 6)
void conv_route_kernel(const float* __restrict__ x,
                       const float* __restrict__ w,
                       const int*   __restrict__ src,
                       float*       __restrict__ out) {
    __shared__ __align__(128) float4 xsb[3][NF4];   // swizzled; [0..7] = halo
    __shared__ __align__(16)  float  wshb[3][K_TAPS];
    __shared__ int slst[MAX_B];
    __shared__ int sh_next;

    const int tid  = threadIdx.x;
    const int lane = tid & 31;
    const int wid  = tid >> 5;

    if (tid < 8) {                                   // halo, never overwritten
#pragma unroll
        for (int b = 0; b < 3; ++b)
            xsb[b][tid] = make_float4(0.f, 0.f, 0.f, 0.f);
    }

    int offs[12];
#pragma unroll
    for (int c = 0; c < 12; ++c) offs[c] = sw(4 * tid + c);
    const int so0 = sw(8 + tid),       so1 = sw(8 + tid + 128);
    const int so2 = sw(8 + tid + 256), so3 = sw(8 + tid + 384);

#define ISSUE(EIDX, B)                                                         \
    {                                                                          \
        int e = slst[EIDX];                                                    \
        const float* r = x + (size_t)src[e] * T_LEN;                           \
        cp16(&xsb[B][so0], r + 4 * tid);                                       \
        cp16(&xsb[B][so1], r + 4 * (tid + 128));                               \
        cp16(&xsb[B][so2], r + 4 * (tid + 256));                               \
        cp16(&xsb[B][so3], r + 4 * (tid + 384));                               \
        if (tid < 8) cp16(&wshb[B][4 * tid], w + e * K_TAPS + 4 * tid);        \
        CP_COMMIT();                                                           \
    }

#define COMPUTE(B)                                                             \
    {                                                                          \
        const float4* xr = xsb[B];                                             \
        const float4* w4 = (const float4*)wshb[B];                             \
        float wf[K_TAPS];                                                      \
        _Pragma("unroll")                                                      \
        for (int q = 0; q < 8; ++q) {                                          \
            float4 wv = w4[q];                                                 \
            wf[4 * q] = wv.x; wf[4 * q + 1] = wv.y;                            \
            wf[4 * q + 2] = wv.z; wf[4 * q + 3] = wv.w;                        \
        }                                                                      \
        _Pragma("unroll")                                                      \
        for (int c = 0; c < 12; ++c) {                                         \
            float4 V = xr[offs[c]];                                            \
            _Pragma("unroll")                                                  \
            for (int d = 0; d < 4; ++d) {                                      \
                const int u  = 4 * c + d;                                      \
                const float xv = f4c(V, d);                                    \
                const int jlo = (u > 32) ? (u - 32) : 0;                       \
                const int jhi = (u - 1 < 15) ? (u - 1) : 15;                   \
                _Pragma("unroll")                                              \
                for (int j = jlo; j <= jhi; ++j)                               \
                    acc[j] += xv * wf[32 + j - u];                             \
            }                                                                  \
        }                                                                      \
    }

    // Last expert of a row: a lone pending cp.async group is NOT completed by
    // wait_group 1 -> use wait_group 0 (also drains before the next row).
#define STEP(B)                                                                \
    {                                                                          \
        if (i + 1 < cnt) { CP_WAIT1(); } else { CP_WAIT0(); }                  \
        __syncthreads();                                                       \
        if (i + 2 < cnt) ISSUE(i + 2, (B + 2) % 3)                             \
        COMPUTE(B)                                                             \
    }

    int row = blockIdx.x;
    while (row < N_ROWS) {
        const int n    = row;
        int cnt        = g_cnt[n];
        if (cnt > MAX_B) cnt = MAX_B;

        if (tid < cnt) slst[tid] = g_lst[n][tid];
        __syncthreads();
        if (tid == 0) g_cnt[n] = 0;                  // reset for next replay

        // Deterministic ordering: sort the list ascending.
        if (cnt <= 32) {
            if (wid == 0) {                          // warp bitonic over 32 slots
                int val = (lane < cnt) ? slst[lane] : 0x7fffffff;
#pragma unroll
                for (int k = 2; k <= 32; k <<= 1) {
#pragma unroll
                    for (int j = k >> 1; j > 0; j >>= 1) {
                        int other = __shfl_xor_sync(0xffffffffu, val, j);
                        bool up    = ((lane & k) == 0);
                        bool lower = ((lane & j) == 0);
                        int mn = min(val, other), mx = max(val, other);
                        val = (lower == up) ? mn : mx;
                    }
                }
                slst[lane] = val;
            }
        } else if (tid == 0) {                       // rare fallback
            for (int a = 1; a < cnt; ++a) {
                int key = slst[a], b = a - 1;
                while (b >= 0 && slst[b] > key) { slst[b + 1] = slst[b]; --b; }
                slst[b + 1] = key;
            }
        }
        __syncthreads();

        float acc[TOUT];
#pragma unroll
        for (int j = 0; j < TOUT; ++j) acc[j] = 0.0f;

        if (cnt > 0) ISSUE(0, 0)
        if (cnt > 1) ISSUE(1, 1)

        int i = 0;
        while (i < cnt) {
            STEP(0) ++i; if (i >= cnt) break;
            STEP(1) ++i; if (i >= cnt) break;
            STEP(2) ++i;
        }

        // Epilogue: out[n] = x[n] + acc
        const float4* xrow = (const float4*)(x + (size_t)n * T_LEN);
        float4*       orow = (float4*)(out + (size_t)n * T_LEN);
#pragma unroll
        for (int p2 = 0; p2 < 4; ++p2) {
            float4 a = xrow[4 * tid + p2];
            a.x += acc[4 * p2 + 0];
            a.y += acc[4 * p2 + 1];
            a.z += acc[4 * p2 + 2];
            a.w += acc[4 * p2 + 3];
            orow[4 * tid + p2] = a;
        }

        if (tid == 0) sh_next = GRID + atomicAdd(&g_ctr, 1);
        __syncthreads();
        row = sh_next;
        __syncthreads();
    }
#undef STEP
#undef COMPUTE
#undef ISSUE
}

// ---------------------------------------------------------------------------
extern "C" void kernel_launch(void* const* d_in, const int* in_sizes, int n_in,
                              void* d_out, int out_size) {
    const float* x   = (const float*)d_in[0];
    const float* w   = (const float*)d_in[1];
    const int*   src = (const int*)d_in[2];
    const int*   dst = (const int*)d_in[3];
    float*       out = (float*)d_out;

    scatter_experts<<<E_NUM / 256, 256>>>(dst);
    conv_route_kernel<<<GRID, TPB>>>(x, w, src, out);
}

// round 15
// speedup vs baseline: 1.6839x; 1.2524x over previous
#include <cuda_runtime.h>

#define N_ROWS 1024
#define T_LEN  2048
#define E_NUM  16384
#define K_TAPS 32
#define TPB    128
#define TOUT   16             // outputs per thread (t0 = 16*tid)
#define MAX_B  96             // max experts per dst bucket
#define NF4    520            // f4 slots per row buffer: 8 halo + 512 row
#define GRID   888            // 148 SMs x 6 resident blocks

__device__ int g_ctr;                       // work-steal cursor
__device__ int g_cnt[N_ROWS];               // experts per dst row (zero-init; conv re-zeros)
__device__ int g_lst[N_ROWS][MAX_B];        // expert ids (unordered; conv rank-sorts)

// Swizzle on float4 index: conflict-free for lane-stride-1 fills and
// lane-stride-4 window loads (bijection, all-distinct bank groups).
__device__ __forceinline__ int sw(int f4) { return f4 ^ ((f4 >> 2) & 7); }

__device__ __forceinline__ float f4c(const float4& v, int d) {
    return d == 0 ? v.x : d == 1 ? v.y : d == 2 ? v.z : v.w;  // d compile-time
}

__device__ __forceinline__ void cp16(void* s, const void* g) {
    unsigned sa = (unsigned)__cvta_generic_to_shared(s);
    asm volatile("cp.async.cg.shared.global [%0], [%1], 16;" :: "r"(sa), "l"(g));
}
#define CP_COMMIT()  asm volatile("cp.async.commit_group;")
#define CP_WAIT1()   asm volatile("cp.async.wait_group 1;")
#define CP_WAIT0()   asm volatile("cp.async.wait_group 0;")

// ---------------------------------------------------------------------------
// Kernel 1: O(E) scatter. One thread per expert; order within a row is
// nondeterministic here (conv rank-sorts). Also resets the work-steal
// cursor. Relies on g_cnt == 0 on entry (module-load zero-init; conv re-zeros
// each row after consuming it, so graph replays see zeros again).
// ---------------------------------------------------------------------------
__global__ __launch_bounds__(256)
void scatter_experts(const int* __restrict__ dst) {
    int e = blockIdx.x * 256 + threadIdx.x;
    if (e == 0) g_ctr = 0;
    if (e < E_NUM) {
        int v = dst[e];
        int pos = atomicAdd(&g_cnt[v], 1);
        if (pos < MAX_B) g_lst[v][pos] = e;
    }
}

// ---------------------------------------------------------------------------
// Kernel 2: persistent conv blocks, 6/SM. Per row: copy list, deterministic
// RANK-BY-COUNTING sort (branch-free, O(cnt) parallel — no serial fallback),
// zero g_cnt[n] for the next replay, then 3-stage cp.async ring of expert
// rows, 1 barrier per expert, weight-shift register FMAs, epilogue
// out = x[n] + acc.
// ---------------------------------------------------------------------------
__global__ __launch_bounds__(TPB, 6)
void conv_route_kernel(const float* __restrict__ x,
                       const float* __restrict__ w,
                       const int*   __restrict__ src,
                       float*       __restrict__ out) {
    __shared__ __align__(128) float4 xsb[3][NF4];   // swizzled; [0..7] = halo
    __shared__ __align__(16)  float  wshb[3][K_TAPS];
    __shared__ int slst[MAX_B];                      // unordered copy
    __shared__ int sord[MAX_B];                      // rank-ordered (ascending e)
    __shared__ int sh_next;

    const int tid = threadIdx.x;

    if (tid < 8) {                                   // halo, never overwritten
#pragma unroll
        for (int b = 0; b < 3; ++b)
            xsb[b][tid] = make_float4(0.f, 0.f, 0.f, 0.f);
    }

    int offs[12];
#pragma unroll
    for (int c = 0; c < 12; ++c) offs[c] = sw(4 * tid + c);
    const int so0 = sw(8 + tid),       so1 = sw(8 + tid + 128);
    const int so2 = sw(8 + tid + 256), so3 = sw(8 + tid + 384);

#define ISSUE(EIDX, B)                                                         \
    {                                                                          \
        int e = sord[EIDX];                                                    \
        const float* r = x + (size_t)src[e] * T_LEN;                           \
        cp16(&xsb[B][so0], r + 4 * tid);                                       \
        cp16(&xsb[B][so1], r + 4 * (tid + 128));                               \
        cp16(&xsb[B][so2], r + 4 * (tid + 256));                               \
        cp16(&xsb[B][so3], r + 4 * (tid + 384));                               \
        if (tid < 8) cp16(&wshb[B][4 * tid], w + e * K_TAPS + 4 * tid);        \
        CP_COMMIT();                                                           \
    }

#define COMPUTE(B)                                                             \
    {                                                                          \
        const float4* xr = xsb[B];                                             \
        const float4* w4 = (const float4*)wshb[B];                             \
        float wf[K_TAPS];                                                      \
        _Pragma("unroll")                                                      \
        for (int q = 0; q < 8; ++q) {                                          \
            float4 wv = w4[q];                                                 \
            wf[4 * q] = wv.x; wf[4 * q + 1] = wv.y;                            \
            wf[4 * q + 2] = wv.z; wf[4 * q + 3] = wv.w;                        \
        }                                                                      \
        _Pragma("unroll")                                                      \
        for (int c = 0; c < 12; ++c) {                                         \
            float4 V = xr[offs[c]];                                            \
            _Pragma("unroll")                                                  \
            for (int d = 0; d < 4; ++d) {                                      \
                const int u  = 4 * c + d;                                      \
                const float xv = f4c(V, d);                                    \
                const int jlo = (u > 32) ? (u - 32) : 0;                       \
                const int jhi = (u - 1 < 15) ? (u - 1) : 15;                   \
                _Pragma("unroll")                                              \
                for (int j = jlo; j <= jhi; ++j)                               \
                    acc[j] += xv * wf[32 + j - u];                             \
            }                                                                  \
        }                                                                      \
    }

    // Last expert of a row: a lone pending cp.async group is NOT completed by
    // wait_group 1 -> use wait_group 0 (also drains before the next row).
#define STEP(B)                                                                \
    {                                                                          \
        if (i + 1 < cnt) { CP_WAIT1(); } else { CP_WAIT0(); }                  \
        __syncthreads();                                                       \
        if (i + 2 < cnt) ISSUE(i + 2, (B + 2) % 3)                             \
        COMPUTE(B)                                                             \
    }

    int row = blockIdx.x;
    while (row < N_ROWS) {
        const int n = row;
        int cnt     = g_cnt[n];
        if (cnt > MAX_B) cnt = MAX_B;

        if (tid < cnt) slst[tid] = g_lst[n][tid];
        __syncthreads();
        if (tid == 0) g_cnt[n] = 0;                  // reset for next replay

        // Deterministic order: rank-by-counting (ids distinct -> bijection).
        if (tid < cnt) {
            int key  = slst[tid];
            int rank = 0;
            for (int j = 0; j < cnt; ++j) rank += (slst[j] < key);
            sord[rank] = key;
        }
        __syncthreads();

        float acc[TOUT];
#pragma unroll
        for (int j = 0; j < TOUT; ++j) acc[j] = 0.0f;

        if (cnt > 0) ISSUE(0, 0)
        if (cnt > 1) ISSUE(1, 1)

        int i = 0;
        while (i < cnt) {
            STEP(0) ++i; if (i >= cnt) break;
            STEP(1) ++i; if (i >= cnt) break;
            STEP(2) ++i;
        }

        // Epilogue: out[n] = x[n] + acc
        const float4* xrow = (const float4*)(x + (size_t)n * T_LEN);
        float4*       orow = (float4*)(out + (size_t)n * T_LEN);
#pragma unroll
        for (int p2 = 0; p2 < 4; ++p2) {
            float4 a = xrow[4 * tid + p2];
            a.x += acc[4 * p2 + 0];
            a.y += acc[4 * p2 + 1];
            a.z += acc[4 * p2 + 2];
            a.w += acc[4 * p2 + 3];
            orow[4 * tid + p2] = a;
        }

        if (tid == 0) sh_next = GRID + atomicAdd(&g_ctr, 1);
        __syncthreads();
        row = sh_next;
        __syncthreads();
    }
#undef STEP
#undef COMPUTE
#undef ISSUE
}

// ---------------------------------------------------------------------------
extern "C" void kernel_launch(void* const* d_in, const int* in_sizes, int n_in,
                              void* d_out, int out_size) {
    const float* x   = (const float*)d_in[0];
    const float* w   = (const float*)d_in[1];
    const int*   src = (const int*)d_in[2];
    const int*   dst = (const int*)d_in[3];
    float*       out = (float*)d_out;

    scatter_experts<<<E_NUM / 256, 256>>>(dst);
    conv_route_kernel<<<GRID, TPB>>>(x, w, src, out);
}